// round 4
// baseline (speedup 1.0000x reference)
#include <cuda_runtime.h>

#define NN 25000
#define NE 400000

#define INV_SQRT3 0.57735026919f
#define INV_SQRT2 0.70710678119f

// ---------------- scratch (device globals; allocation-free) ----------------
__device__ float4 d_g_s  [NN * 16];   // s   = s_in @ W1_0 /8           (N,64)
__device__ float4 d_g_v  [NN * 24];   // v   = v_in . W1_1 /sqrt32      (N,32,3) [u*3+c]
__device__ float4 d_g_scs[NN * 16];   // sc_s                           (N,64)
__device__ float4 d_g_scv[NN * 24];   // sc_v                           (N,96)  [u*3+c]
__device__ float4 d_g_ns [NN * 24];   // scatter accum s-part           (N,96)
__device__ float4 d_g_nv [NN * 96];   // scatter accum v-part           (N,3,128) [c][u]
__device__ float  d_W1T[64 * 8];      // Wfc1^T, prescaled 1/sqrt(8)
__device__ float  d_W2T[64 * 64];     // Wfc2^T, prescaled 1/8
__device__ float  d_W3T[224 * 64];    // Wfc3^T, prescaled WS (+INV_SQRT3/2 rows)

// ---------------- f32x2 helpers ----------------
#define FMA2(d, a, b) \
    asm("fma.rn.f32x2 %0, %1, %2, %0;" : "+l"(d) : "l"(a), "l"(b))
#define ADD2(d, a, b) \
    asm("add.rn.f32x2 %0, %1, %2;" : "=l"(d) : "l"(a), "l"(b))
#define PACK2(d, lo, hi) \
    asm("mov.b64 %0, {%1, %2};" : "=l"(d) : "f"(lo), "f"(hi))
#define UNPACK2(lo, hi, s) \
    asm("mov.b64 {%0, %1}, %2;" : "=f"(lo), "=f"(hi) : "l"(s))

__device__ __forceinline__ float silu_f(float x) {
    return x / (1.0f + __expf(-x));
}

// single-edge dot of 64 floats (h packed as 32 f32x2), w = 16B-aligned smem row
__device__ __forceinline__ float dot64x2(const unsigned long long* h,
                                         const float* w) {
    unsigned long long a0 = 0ull, a1 = 0ull, a2 = 0ull, a3 = 0ull;
    const ulonglong2* q = reinterpret_cast<const ulonglong2*>(w);
#pragma unroll
    for (int k = 0; k < 8; ++k) {
        ulonglong2 w0 = q[2 * k];
        ulonglong2 w1 = q[2 * k + 1];
        FMA2(a0, h[4 * k + 0], w0.x);
        FMA2(a1, h[4 * k + 1], w0.y);
        FMA2(a2, h[4 * k + 2], w1.x);
        FMA2(a3, h[4 * k + 3], w1.y);
    }
    ADD2(a0, a0, a1);
    ADD2(a2, a2, a3);
    ADD2(a0, a0, a2);
    float lo, hi;
    UNPACK2(lo, hi, a0);
    return lo + hi;
}

// dual-edge dot: one weight load feeds both edges (halves LDS traffic)
__device__ __forceinline__ void dot64x2_dual(const unsigned long long* hA,
                                             const unsigned long long* hB,
                                             const float* w,
                                             float& ra, float& rb) {
    unsigned long long a0 = 0ull, a1 = 0ull, b0 = 0ull, b1 = 0ull;
    const ulonglong2* q = reinterpret_cast<const ulonglong2*>(w);
#pragma unroll
    for (int k = 0; k < 16; ++k) {
        ulonglong2 ww = q[k];
        FMA2(a0, hA[2 * k + 0], ww.x);
        FMA2(a1, hA[2 * k + 1], ww.y);
        FMA2(b0, hB[2 * k + 0], ww.x);
        FMA2(b1, hB[2 * k + 1], ww.y);
    }
    ADD2(a0, a0, a1);
    ADD2(b0, b0, b1);
    float lo, hi;
    UNPACK2(lo, hi, a0); ra = lo + hi;
    UNPACK2(lo, hi, b0); rb = lo + hi;
}

__device__ __forceinline__ void red4(float* p, float a, float b, float c, float d) {
    asm volatile("red.global.add.v4.f32 [%0], {%1,%2,%3,%4};"
                 :: "l"(p), "f"(a), "f"(b), "f"(c), "f"(d) : "memory");
}

// edge MLP 8 -> 64 -> 64 (h1 lives only inside; h2 returned packed)
__device__ __forceinline__ void edge_mlp(int e,
                                         const float* __restrict__ eattr,
                                         const float* sW1, const float* sW2,
                                         unsigned long long* h2p) {
    float att[8];
    const float4* ap = reinterpret_cast<const float4*>(eattr + (size_t)e * 8);
    float4 a0 = __ldg(ap), a1 = __ldg(ap + 1);
    att[0] = a0.x; att[1] = a0.y; att[2] = a0.z; att[3] = a0.w;
    att[4] = a1.x; att[5] = a1.y; att[6] = a1.z; att[7] = a1.w;

    unsigned long long h1p[32];
#pragma unroll
    for (int p = 0; p < 32; ++p) {
        float r[2];
#pragma unroll
        for (int i = 0; i < 2; ++i) {
            int j = 2 * p + i;
            float4 q0 = *reinterpret_cast<const float4*>(sW1 + j * 8);
            float4 q1 = *reinterpret_cast<const float4*>(sW1 + j * 8 + 4);
            float a = att[0] * q0.x + att[1] * q0.y + att[2] * q0.z + att[3] * q0.w
                    + att[4] * q1.x + att[5] * q1.y + att[6] * q1.z + att[7] * q1.w;
            r[i] = silu_f(a);
        }
        PACK2(h1p[p], r[0], r[1]);
    }
#pragma unroll
    for (int p = 0; p < 32; ++p) {
        float a = silu_f(dot64x2(h1p, sW2 + (2 * p) * 64));
        float b = silu_f(dot64x2(h1p, sW2 + (2 * p + 1) * 64));
        PACK2(h2p[p], a, b);
    }
}

// ---------------- kernel 0: transpose + prescale MLP weights ----------------
__global__ void k_transpose(const float* __restrict__ Wfc1,
                            const float* __restrict__ Wfc2,
                            const float* __restrict__ Wfc3) {
    int t = threadIdx.x;
    for (int i = t; i < 64 * 8; i += 256)
        d_W1T[i] = Wfc1[(i & 7) * 64 + (i >> 3)] * 0.3535533906f;
    for (int i = t; i < 64 * 64; i += 256)
        d_W2T[i] = Wfc2[(i & 63) * 64 + (i >> 6)] * 0.125f;
    for (int i = t; i < 224 * 64; i += 256) {
        int j = i >> 6;
        float s = 0.03125f;  // (1/sqrt(64)) * (1/sqrt(16))
        if (j >= 192)      s *= INV_SQRT2;
        else if (j >= 160) s *= INV_SQRT3;
        d_W3T[i] = Wfc3[(i & 63) * 224 + j] * s;
    }
}

// ---------------- kernel 1: zero accumulators ----------------
__global__ void k_zero() {
    int i = blockIdx.x * blockDim.x + threadIdx.x;
    int stride = gridDim.x * blockDim.x;
    float4 z = make_float4(0.f, 0.f, 0.f, 0.f);
    const int tot = NN * 24 + NN * 96;
    for (; i < tot; i += stride) {
        if (i < NN * 24) d_g_ns[i] = z;
        else             d_g_nv[i - NN * 24] = z;
    }
}

// ---------------- kernel 2: node prep, warp-per-node ----------------
__global__ void __launch_bounds__(256) k_prep(const float* __restrict__ nh,
                                              const float* __restrict__ W1_0,
                                              const float* __restrict__ W1_1,
                                              const float* __restrict__ Wsc0,
                                              const float* __restrict__ Wsc1) {
    __shared__ float sW10[4096], sWsc0[4096], sW11[1024], sWsc1[1024], sIn[1280];
    int t = threadIdx.x;
    for (int i = t; i < 4096; i += 256) { sW10[i] = W1_0[i]; sWsc0[i] = Wsc0[i]; }
    for (int i = t; i < 1024; i += 256) { sW11[i] = W1_1[i]; sWsc1[i] = Wsc1[i]; }
    int wid = t >> 5, l = t & 31;
    int n = blockIdx.x * 8 + wid;
    for (int i = l; i < 160; i += 32)
        sIn[wid * 160 + i] = nh[(size_t)n * 160 + i];
    __syncthreads();

    const float* row = sIn + wid * 160;
    float* gs  = (float*)d_g_s;
    float* gv  = (float*)d_g_v;
    float* gss = (float*)d_g_scs;
    float* gsv = (float*)d_g_scv;

#pragma unroll
    for (int r = 0; r < 2; ++r) {
        int o = l + r * 32;
        float a = 0.f, b = 0.f;
#pragma unroll 8
        for (int u = 0; u < 64; ++u) {
            float x = row[u];
            a += x * sW10[u * 64 + o];
            b += x * sWsc0[u * 64 + o];
        }
        gs [(size_t)n * 64 + o] = a * 0.125f;
        gss[(size_t)n * 64 + o] = b * 0.125f;
    }
#pragma unroll
    for (int r = 0; r < 3; ++r) {
        int o = l + r * 32;
        int up = o / 3, c = o - up * 3;
        float a = 0.f, b = 0.f;
#pragma unroll 8
        for (int u = 0; u < 32; ++u) {
            float x = row[64 + u * 3 + c];
            a += x * sW11[u * 32 + up];
            b += x * sWsc1[u * 32 + up];
        }
        gv [(size_t)n * 96 + o] = a * 0.1767766953f;
        gsv[(size_t)n * 96 + o] = b * 0.1767766953f;
    }
}

// ---------------- kernel 3: edge MLP + messages + scatter (2 edges/thread) ----
__global__ void __launch_bounds__(128) k_edge(const int* __restrict__ ei,
                                              const float* __restrict__ esh,
                                              const float* __restrict__ eattr) {
    extern __shared__ float sm[];
    float* sW3 = sm;            // 14336 floats [j][k] j<224 (prescaled)
    float* sW2 = sm + 14336;    // 4096 floats  [j][k] j<64  (prescaled)
    float* sW1 = sm + 18432;    // 512 floats   [j][k] j<64,k<8 (prescaled)
    int t = threadIdx.x;
    for (int i = t; i < 14336; i += 128) sW3[i] = d_W3T[i];
    for (int i = t; i < 4096;  i += 128) sW2[i] = d_W2T[i];
    for (int i = t; i < 512;   i += 128) sW1[i] = d_W1T[i];
    __syncthreads();

    int eA = blockIdx.x * 256 + t;        // always < NE (grid covers NE+128)
    int eB = eA + 128;
    bool hasB = (eB < NE);
    int eBc = hasB ? eB : eA;

    unsigned long long h2pA[32], h2pB[32];
    edge_mlp(eA,  eattr, sW1, sW2, h2pA);
    edge_mlp(eBc, eattr, sW1, sW2, h2pB);

    int srcA = __ldg(ei + eA),  dstA = __ldg(ei + NE + eA);
    int srcB = __ldg(ei + eBc), dstB = __ldg(ei + NE + eBc);
    float4 shA = __ldg(reinterpret_cast<const float4*>(esh + (size_t)eA * 4));
    float4 shB = __ldg(reinterpret_cast<const float4*>(esh + (size_t)eBc * 4));

    const float* sdA = (const float*)d_g_s + (size_t)dstA * 64;
    const float* sdB = (const float*)d_g_s + (size_t)dstB * 64;
    const float* vdA = (const float*)d_g_v + (size_t)dstA * 96;
    const float* vdB = (const float*)d_g_v + (size_t)dstB * 96;
    float* nspA = (float*)d_g_ns + (size_t)srcA * 96;
    float* nspB = (float*)d_g_ns + (size_t)srcB * 96;
    float* nvpA = (float*)d_g_nv + (size_t)srcA * 384;
    float* nvpB = (float*)d_g_nv + (size_t)srcB * 384;

    // ---- m0 (ns[0:64]) and mv0 (nv[c][0:64]) ----
#pragma unroll 1
    for (int g = 0; g < 16; ++g) {
        float4 s4A = __ldg(reinterpret_cast<const float4*>(sdA) + g);
        float4 s4B = __ldg(reinterpret_cast<const float4*>(sdB) + g);
        float sA[4] = {s4A.x, s4A.y, s4A.z, s4A.w};
        float sB[4] = {s4B.x, s4B.y, s4B.z, s4B.w};
        float m0A[4], w1A[4], m0B[4], w1B[4];
#pragma unroll
        for (int i = 0; i < 4; ++i) {
            int j = g * 4 + i;
            float w0a, w0b, w1a, w1b;
            dot64x2_dual(h2pA, h2pB, sW3 + j * 64,        w0a, w0b);
            dot64x2_dual(h2pA, h2pB, sW3 + (64 + j) * 64, w1a, w1b);
            m0A[i] = w0a * sA[i] * shA.x;
            m0B[i] = w0b * sB[i] * shB.x;
            w1A[i] = w1a * sA[i];
            w1B[i] = w1b * sB[i];
        }
        red4(nspA + g * 4, m0A[0], m0A[1], m0A[2], m0A[3]);
        red4(nvpA +       g * 4, w1A[0] * shA.y, w1A[1] * shA.y, w1A[2] * shA.y, w1A[3] * shA.y);
        red4(nvpA + 128 + g * 4, w1A[0] * shA.z, w1A[1] * shA.z, w1A[2] * shA.z, w1A[3] * shA.z);
        red4(nvpA + 256 + g * 4, w1A[0] * shA.w, w1A[1] * shA.w, w1A[2] * shA.w, w1A[3] * shA.w);
        if (hasB) {
            red4(nspB + g * 4, m0B[0], m0B[1], m0B[2], m0B[3]);
            red4(nvpB +       g * 4, w1B[0] * shB.y, w1B[1] * shB.y, w1B[2] * shB.y, w1B[3] * shB.y);
            red4(nvpB + 128 + g * 4, w1B[0] * shB.z, w1B[1] * shB.z, w1B[2] * shB.z, w1B[3] * shB.z);
            red4(nvpB + 256 + g * 4, w1B[0] * shB.w, w1B[1] * shB.w, w1B[2] * shB.w, w1B[3] * shB.w);
        }
    }

    // ---- m1 (ns[64:96]), mv1 (nv[c][64:96]), mv2 (nv[c][96:128]) ----
#pragma unroll 1
    for (int g = 0; g < 8; ++g) {
        const float4* vbA = reinterpret_cast<const float4*>(vdA + g * 12);
        const float4* vbB = reinterpret_cast<const float4*>(vdB + g * 12);
        float4 a0 = __ldg(vbA), a1 = __ldg(vbA + 1), a2 = __ldg(vbA + 2);
        float4 b0 = __ldg(vbB), b1 = __ldg(vbB + 1), b2 = __ldg(vbB + 2);
        float vvA[12] = {a0.x, a0.y, a0.z, a0.w, a1.x, a1.y, a1.z, a1.w,
                         a2.x, a2.y, a2.z, a2.w};
        float vvB[12] = {b0.x, b0.y, b0.z, b0.w, b1.x, b1.y, b1.z, b1.w,
                         b2.x, b2.y, b2.z, b2.w};
        float m1A[4], mv1A[3][4], mv2A[3][4];
        float m1B[4], mv1B[3][4], mv2B[3][4];
#pragma unroll
        for (int i = 0; i < 4; ++i) {
            int u = g * 4 + i;
            float w2a, w2b, w3a, w3b, w4a, w4b;
            dot64x2_dual(h2pA, h2pB, sW3 + (128 + u) * 64, w2a, w2b);
            dot64x2_dual(h2pA, h2pB, sW3 + (160 + u) * 64, w3a, w3b);  // incl INV_SQRT3
            dot64x2_dual(h2pA, h2pB, sW3 + (192 + u) * 64, w4a, w4b);  // incl INV_SQRT2
            {
                float vx = vvA[i * 3], vy = vvA[i * 3 + 1], vz = vvA[i * 3 + 2];
                m1A[i] = w3a * (vx * shA.y + vy * shA.z + vz * shA.w);
                mv1A[0][i] = w2a * vx * shA.x;
                mv1A[1][i] = w2a * vy * shA.x;
                mv1A[2][i] = w2a * vz * shA.x;
                mv2A[0][i] = w4a * (vy * shA.w - vz * shA.z);
                mv2A[1][i] = w4a * (vz * shA.y - vx * shA.w);
                mv2A[2][i] = w4a * (vx * shA.z - vy * shA.y);
            }
            {
                float vx = vvB[i * 3], vy = vvB[i * 3 + 1], vz = vvB[i * 3 + 2];
                m1B[i] = w3b * (vx * shB.y + vy * shB.z + vz * shB.w);
                mv1B[0][i] = w2b * vx * shB.x;
                mv1B[1][i] = w2b * vy * shB.x;
                mv1B[2][i] = w2b * vz * shB.x;
                mv2B[0][i] = w4b * (vy * shB.w - vz * shB.z);
                mv2B[1][i] = w4b * (vz * shB.y - vx * shB.w);
                mv2B[2][i] = w4b * (vx * shB.z - vy * shB.y);
            }
        }
        red4(nspA + 64 + g * 4, m1A[0], m1A[1], m1A[2], m1A[3]);
#pragma unroll
        for (int c = 0; c < 3; ++c) {
            red4(nvpA + c * 128 + 64 + g * 4, mv1A[c][0], mv1A[c][1], mv1A[c][2], mv1A[c][3]);
            red4(nvpA + c * 128 + 96 + g * 4, mv2A[c][0], mv2A[c][1], mv2A[c][2], mv2A[c][3]);
        }
        if (hasB) {
            red4(nspB + 64 + g * 4, m1B[0], m1B[1], m1B[2], m1B[3]);
#pragma unroll
            for (int c = 0; c < 3; ++c) {
                red4(nvpB + c * 128 + 64 + g * 4, mv1B[c][0], mv1B[c][1], mv1B[c][2], mv1B[c][3]);
                red4(nvpB + c * 128 + 96 + g * 4, mv2B[c][0], mv2B[c][1], mv2B[c][2], mv2B[c][3]);
            }
        }
    }
}

// ---------------- kernel 4: output projection + skip + RMS, warp-per-node ----
__global__ void __launch_bounds__(256) k_out(float* __restrict__ out,
                                             const float* __restrict__ W2_0,
                                             const float* __restrict__ W2_1,
                                             const float* __restrict__ g0,
                                             const float* __restrict__ g1) {
    extern __shared__ float smo[];
    float* sW20 = smo;           // 6144
    float* sW21 = smo + 6144;    // 4096
    float* sAcc = smo + 10240;   // 8 * 480
    int t = threadIdx.x;
    for (int i = t; i < 6144; i += 256) sW20[i] = W2_0[i];
    for (int i = t; i < 4096; i += 256) sW21[i] = W2_1[i];

    const float* gns = (const float*)d_g_ns;
    const float* gnv = (const float*)d_g_nv;
    const float* gss = (const float*)d_g_scs;
    const float* gsv = (const float*)d_g_scv;

    int wid = t >> 5, l = t & 31;
    int n = blockIdx.x * 8 + wid;
    float* acc = sAcc + wid * 480;
    for (int i = l; i < 480; i += 32)
        acc[i] = (i < 96) ? gns[(size_t)n * 96 + i]
                          : gnv[(size_t)n * 384 + i - 96];
    __syncthreads();

    float vs[2], vv[3];
    float ssq_s = 0.f, ssq_v = 0.f;
#pragma unroll
    for (int r = 0; r < 2; ++r) {
        int o = l + r * 32;
        float a = 0.f;
#pragma unroll 8
        for (int k = 0; k < 96; ++k) a += acc[k] * sW20[k * 64 + o];
        float val = a * 0.1020620726f + gss[(size_t)n * 64 + o];
        vs[r] = val;
        ssq_s += val * val;
    }
#pragma unroll
    for (int r = 0; r < 3; ++r) {
        int o = l + r * 32;
        int up = o / 3, c = o - up * 3;
        float a = 0.f;
#pragma unroll 8
        for (int u = 0; u < 128; ++u) a += acc[96 + c * 128 + u] * sW21[u * 32 + up];
        float val = a * 0.0883883476f + gsv[(size_t)n * 96 + o];
        vv[r] = val;
        ssq_v += val * val;
    }
#pragma unroll
    for (int d = 16; d; d >>= 1) {
        ssq_s += __shfl_xor_sync(0xffffffffu, ssq_s, d);
        ssq_v += __shfl_xor_sync(0xffffffffu, ssq_v, d);
    }
    float rs = rsqrtf(ssq_s * (1.0f / 64.0f) + 1e-5f);
    float rv = rsqrtf(ssq_v * (1.0f / 32.0f) + 1e-5f);
#pragma unroll
    for (int r = 0; r < 2; ++r) {
        int o = l + r * 32;
        out[(size_t)n * 160 + o] = vs[r] * rs * g0[o];
    }
#pragma unroll
    for (int r = 0; r < 3; ++r) {
        int o = l + r * 32;
        out[(size_t)n * 160 + 64 + o] = vv[r] * rv * g1[o / 3];
    }
}

// ---------------- launch ----------------
extern "C" void kernel_launch(void* const* d_in, const int* in_sizes, int n_in,
                              void* d_out, int out_size) {
    const float* nh    = (const float*)d_in[0];
    const int*   ei    = (const int*)  d_in[1];
    const float* esh   = (const float*)d_in[2];
    const float* eattr = (const float*)d_in[3];
    const float* W1_0  = (const float*)d_in[4];
    const float* W1_1  = (const float*)d_in[5];
    const float* Wfc1  = (const float*)d_in[6];
    const float* Wfc2  = (const float*)d_in[7];
    const float* Wfc3  = (const float*)d_in[8];
    const float* W2_0  = (const float*)d_in[9];
    const float* W2_1  = (const float*)d_in[10];
    const float* Wsc0  = (const float*)d_in[11];
    const float* Wsc1  = (const float*)d_in[12];
    const float* g0    = (const float*)d_in[13];
    const float* g1    = (const float*)d_in[14];
    float* out = (float*)d_out;

    cudaFuncSetAttribute(k_edge, cudaFuncAttributeMaxDynamicSharedMemorySize, 75776);
    cudaFuncSetAttribute(k_out, cudaFuncAttributeMaxDynamicSharedMemorySize, 56320);

    k_transpose<<<1, 256>>>(Wfc1, Wfc2, Wfc3);
    k_zero<<<1024, 256>>>();
    k_prep<<<3125, 256>>>(nh, W1_0, W1_1, Wsc0, Wsc1);
    k_edge<<<1563, 128, 75776>>>(ei, esh, eattr);   // 2 edges per thread
    k_out<<<3125, 256, 56320>>>(out, W2_0, W2_1, g0, g1);
}

// round 5
// speedup vs baseline: 1.0902x; 1.0902x over previous
#include <cuda_runtime.h>

#define NN 25000
#define NE 400000

#define INV_SQRT3 0.57735026919f
#define INV_SQRT2 0.70710678119f

// ---------------- scratch (device globals; allocation-free) ----------------
__device__ float4 d_g_s  [NN * 16];   // s   = s_in @ W1_0 /8           (N,64)
__device__ float4 d_g_v  [NN * 24];   // v   = v_in . W1_1 /sqrt32      (N,32,3) [u*3+c]
__device__ float4 d_g_scs[NN * 16];   // sc_s                           (N,64)
__device__ float4 d_g_scv[NN * 24];   // sc_v                           (N,96)  [u*3+c]
__device__ float4 d_g_ns [NN * 24];   // scatter accum s-part           (N,96)
__device__ float4 d_g_nv [NN * 96];   // scatter accum v-part           (N,3,128) [c][u]
__device__ float  d_W1T[64 * 8];      // Wfc1^T [k][m], prescaled 1/sqrt(8)
__device__ float  d_W2K[64 * 64];     // Wfc2 k-major [k][j], prescaled 1/8
__device__ float  d_W3T[224 * 64];    // Wfc3^T [j][k], prescaled WS (+INV_SQRT3/2)

// ---------------- f32x2 helpers ----------------
#define FMA2(d, a, b) \
    asm("fma.rn.f32x2 %0, %1, %2, %0;" : "+l"(d) : "l"(a), "l"(b))
#define ADD2(d, a, b) \
    asm("add.rn.f32x2 %0, %1, %2;" : "=l"(d) : "l"(a), "l"(b))
#define PACK2(d, lo, hi) \
    asm("mov.b64 %0, {%1, %2};" : "=l"(d) : "f"(lo), "f"(hi))
#define UNPACK2(lo, hi, s) \
    asm("mov.b64 {%0, %1}, %2;" : "=f"(lo), "=f"(hi) : "l"(s))

__device__ __forceinline__ float silu_f(float x) {
    return x / (1.0f + __expf(-x));
}

// dot of 64 floats: h packed as 32 f32x2 pairs, w = 16B-aligned smem row
__device__ __forceinline__ float dot64x2(const unsigned long long* h,
                                         const float* w) {
    unsigned long long a0 = 0ull, a1 = 0ull, a2 = 0ull, a3 = 0ull;
    const ulonglong2* q = reinterpret_cast<const ulonglong2*>(w);
#pragma unroll
    for (int k = 0; k < 8; ++k) {
        ulonglong2 w0 = q[2 * k];
        ulonglong2 w1 = q[2 * k + 1];
        FMA2(a0, h[4 * k + 0], w0.x);
        FMA2(a1, h[4 * k + 1], w0.y);
        FMA2(a2, h[4 * k + 2], w1.x);
        FMA2(a3, h[4 * k + 3], w1.y);
    }
    ADD2(a0, a0, a1);
    ADD2(a2, a2, a3);
    ADD2(a0, a0, a2);
    float lo, hi;
    UNPACK2(lo, hi, a0);
    return lo + hi;
}

__device__ __forceinline__ void red4(float* p, float a, float b, float c, float d) {
    asm volatile("red.global.add.v4.f32 [%0], {%1,%2,%3,%4};"
                 :: "l"(p), "f"(a), "f"(b), "f"(c), "f"(d) : "memory");
}

// ---------------- kernel 0: zero accumulators + transpose/prescale weights ---
__global__ void k_pre(const float* __restrict__ Wfc1,
                      const float* __restrict__ Wfc2,
                      const float* __restrict__ Wfc3) {
    int i = blockIdx.x * 256 + threadIdx.x;
    const int NZ = NN * 120;   // float4 count of (ns + nv)
    if (i < NZ) {
        float4 z = make_float4(0.f, 0.f, 0.f, 0.f);
        if (i < NN * 24) d_g_ns[i] = z;
        else             d_g_nv[i - NN * 24] = z;
    } else {
        int j = i - NZ;
        if (j < 512) {
            d_W1T[j] = Wfc1[(j & 7) * 64 + (j >> 3)] * 0.3535533906f;
        } else if (j < 512 + 4096) {
            int k = j - 512;
            d_W2K[k] = Wfc2[k] * 0.125f;     // already k-major
        } else if (j < 512 + 4096 + 14336) {
            int k = j - 4608;
            int row = k >> 6;
            float s = 0.03125f;  // (1/sqrt(64)) * (1/sqrt(16))
            if (row >= 192)      s *= INV_SQRT2;
            else if (row >= 160) s *= INV_SQRT3;
            d_W3T[k] = Wfc3[(k & 63) * 224 + row] * s;
        }
    }
}

// ---------------- kernel 2: node prep, persistent warp-per-node ----------------
__global__ void __launch_bounds__(256) k_prep(const float* __restrict__ nh,
                                              const float* __restrict__ W1_0,
                                              const float* __restrict__ W1_1,
                                              const float* __restrict__ Wsc0,
                                              const float* __restrict__ Wsc1) {
    __shared__ float sW10[4096], sWsc0[4096], sW11[1024], sWsc1[1024], sIn[1280];
    int t = threadIdx.x;
    for (int i = t; i < 4096; i += 256) { sW10[i] = W1_0[i]; sWsc0[i] = Wsc0[i]; }
    for (int i = t; i < 1024; i += 256) { sW11[i] = W1_1[i]; sWsc1[i] = Wsc1[i]; }
    __syncthreads();

    int wid = t >> 5, l = t & 31;
    float* gs  = (float*)d_g_s;
    float* gv  = (float*)d_g_v;
    float* gss = (float*)d_g_scs;
    float* gsv = (float*)d_g_scv;
    float* row = sIn + wid * 160;

    for (int it = 0; it < 8; ++it) {
        int n = blockIdx.x * 64 + it * 8 + wid;
        if (n >= NN) break;
        {
            const float4* src = reinterpret_cast<const float4*>(nh + (size_t)n * 160);
            float4* dst = reinterpret_cast<float4*>(row);
            for (int i = l; i < 40; i += 32) dst[i] = __ldg(src + i);
        }
        __syncwarp();
#pragma unroll
        for (int r = 0; r < 2; ++r) {
            int o = l + r * 32;
            float a = 0.f, b = 0.f;
#pragma unroll 8
            for (int u = 0; u < 64; ++u) {
                float x = row[u];
                a += x * sW10[u * 64 + o];
                b += x * sWsc0[u * 64 + o];
            }
            gs [(size_t)n * 64 + o] = a * 0.125f;
            gss[(size_t)n * 64 + o] = b * 0.125f;
        }
#pragma unroll
        for (int r = 0; r < 3; ++r) {
            int o = l + r * 32;
            int up = o / 3, c = o - up * 3;
            float a = 0.f, b = 0.f;
#pragma unroll 8
            for (int u = 0; u < 32; ++u) {
                float x = row[64 + u * 3 + c];
                a += x * sW11[u * 32 + up];
                b += x * sWsc1[u * 32 + up];
            }
            gv [(size_t)n * 96 + o] = a * 0.1767766953f;
            gsv[(size_t)n * 96 + o] = b * 0.1767766953f;
        }
        __syncwarp();
    }
}

// ---------------- kernel 3: edge MLP + messages + scatter ----------------
// Phased smem: [sW2K | sW1] live only during the MLP phase, then the same
// region is overwritten with sW3 for the w-phase. 57344 B total.
__global__ void __launch_bounds__(128, 4) k_edge(const int* __restrict__ ei,
                                                 const float* __restrict__ esh,
                                                 const float* __restrict__ eattr) {
    extern __shared__ float sm[];
    float* sW2K = sm;          // 4096 floats  [k][j] (phase 1)
    float* sW1  = sm + 4096;   // 512 floats   [k][m] (phase 1)
    float* sW3  = sm;          // 14336 floats [j][k] (phase 2)
    int t = threadIdx.x;
    for (int i = t; i < 4096; i += 128) sW2K[i] = d_W2K[i];
    for (int i = t; i < 512;  i += 128) sW1[i]  = d_W1T[i];
    __syncthreads();

    int e = blockIdx.x * 128 + t;   // NE = 3125*128 exactly

    // ---- edge MLP, k-outer: h1[k] computed just-in-time, h1 never stored ----
    float att0, att1, att2, att3, att4, att5, att6, att7;
    {
        const float4* ap = reinterpret_cast<const float4*>(eattr + (size_t)e * 8);
        float4 a0 = __ldg(ap), a1 = __ldg(ap + 1);
        att0 = a0.x; att1 = a0.y; att2 = a0.z; att3 = a0.w;
        att4 = a1.x; att5 = a1.y; att6 = a1.z; att7 = a1.w;
    }
    unsigned long long h2p[32];
#pragma unroll
    for (int p = 0; p < 32; ++p) h2p[p] = 0ull;
#pragma unroll 4
    for (int k = 0; k < 64; ++k) {
        float4 q0 = *reinterpret_cast<const float4*>(sW1 + k * 8);
        float4 q1 = *reinterpret_cast<const float4*>(sW1 + k * 8 + 4);
        float a = att0 * q0.x + att1 * q0.y + att2 * q0.z + att3 * q0.w
                + att4 * q1.x + att5 * q1.y + att6 * q1.z + att7 * q1.w;
        float h = silu_f(a);
        unsigned long long hkk;
        PACK2(hkk, h, h);
        const ulonglong2* q = reinterpret_cast<const ulonglong2*>(sW2K + k * 64);
#pragma unroll
        for (int i = 0; i < 16; ++i) {
            ulonglong2 ww = q[i];
            FMA2(h2p[2 * i],     hkk, ww.x);
            FMA2(h2p[2 * i + 1], hkk, ww.y);
        }
    }
#pragma unroll
    for (int p = 0; p < 32; ++p) {
        float lo, hi;
        UNPACK2(lo, hi, h2p[p]);
        PACK2(h2p[p], silu_f(lo), silu_f(hi));
    }

    __syncthreads();   // done reading sW1/sW2K
    for (int i = t; i < 14336; i += 128) sW3[i] = d_W3T[i];
    __syncthreads();

    int src = __ldg(ei + e);
    int dst = __ldg(ei + NE + e);
    float4 sh = __ldg(reinterpret_cast<const float4*>(esh + (size_t)e * 4));
    float sh0 = sh.x, shx = sh.y, shy = sh.z, shz = sh.w;

    const float* sd  = (const float*)d_g_s + (size_t)dst * 64;
    const float* vd  = (const float*)d_g_v + (size_t)dst * 96;
    float*       nsp = (float*)d_g_ns + (size_t)src * 96;
    float*       nvp = (float*)d_g_nv + (size_t)src * 384;

    // ---- m0 (ns[0:64]) and mv0 (nv[c][0:64]) ----
#pragma unroll 1
    for (int g = 0; g < 16; ++g) {
        float4 s4 = __ldg(reinterpret_cast<const float4*>(sd) + g);
        float sdl[4]  = {s4.x, s4.y, s4.z, s4.w};
        float sdl0[4] = {s4.x * sh0, s4.y * sh0, s4.z * sh0, s4.w * sh0};
        float m0[4], w1s[4];
#pragma unroll
        for (int i = 0; i < 4; ++i) {
            int j = g * 4 + i;
            float w0 = dot64x2(h2p, sW3 + j * 64);
            float w1 = dot64x2(h2p, sW3 + (64 + j) * 64);
            m0[i]  = w0 * sdl0[i];
            w1s[i] = w1 * sdl[i];
        }
        red4(nsp + g * 4, m0[0], m0[1], m0[2], m0[3]);
        red4(nvp +       g * 4, w1s[0] * shx, w1s[1] * shx, w1s[2] * shx, w1s[3] * shx);
        red4(nvp + 128 + g * 4, w1s[0] * shy, w1s[1] * shy, w1s[2] * shy, w1s[3] * shy);
        red4(nvp + 256 + g * 4, w1s[0] * shz, w1s[1] * shz, w1s[2] * shz, w1s[3] * shz);
    }

    // ---- m1 (ns[64:96]), mv1 (nv[c][64:96]), mv2 (nv[c][96:128]) ----
#pragma unroll 1
    for (int g = 0; g < 8; ++g) {
        const float4* vb = reinterpret_cast<const float4*>(vd + g * 12);
        float4 b0 = __ldg(vb), b1 = __ldg(vb + 1), b2 = __ldg(vb + 2);
        float vv[12] = {b0.x, b0.y, b0.z, b0.w, b1.x, b1.y, b1.z, b1.w,
                        b2.x, b2.y, b2.z, b2.w};
        float m1[4], mv1[3][4], mv2[3][4];
#pragma unroll
        for (int i = 0; i < 4; ++i) {
            int u = g * 4 + i;
            float w2 = dot64x2(h2p, sW3 + (128 + u) * 64);
            float w3 = dot64x2(h2p, sW3 + (160 + u) * 64);  // incl INV_SQRT3
            float w4 = dot64x2(h2p, sW3 + (192 + u) * 64);  // incl INV_SQRT2
            float vx = vv[i * 3], vy = vv[i * 3 + 1], vz = vv[i * 3 + 2];
            m1[i] = w3 * (vx * shx + vy * shy + vz * shz);
            mv1[0][i] = w2 * vx * sh0;
            mv1[1][i] = w2 * vy * sh0;
            mv1[2][i] = w2 * vz * sh0;
            mv2[0][i] = w4 * (vy * shz - vz * shy);
            mv2[1][i] = w4 * (vz * shx - vx * shz);
            mv2[2][i] = w4 * (vx * shy - vy * shx);
        }
        red4(nsp + 64 + g * 4, m1[0], m1[1], m1[2], m1[3]);
#pragma unroll
        for (int c = 0; c < 3; ++c) {
            red4(nvp + c * 128 + 64 + g * 4, mv1[c][0], mv1[c][1], mv1[c][2], mv1[c][3]);
            red4(nvp + c * 128 + 96 + g * 4, mv2[c][0], mv2[c][1], mv2[c][2], mv2[c][3]);
        }
    }
}

// ---------------- kernel 4: output projection + skip + RMS, persistent ----
__global__ void __launch_bounds__(256) k_out(float* __restrict__ out,
                                             const float* __restrict__ W2_0,
                                             const float* __restrict__ W2_1,
                                             const float* __restrict__ g0,
                                             const float* __restrict__ g1) {
    extern __shared__ float smo[];
    float* sW20 = smo;           // 6144
    float* sW21 = smo + 6144;    // 4096
    float* sG   = smo + 10240;   // 96 (g0 64 + g1 32)
    float* sAcc = smo + 10368;   // 8 * 480
    int t = threadIdx.x;
    for (int i = t; i < 6144; i += 256) sW20[i] = W2_0[i];
    for (int i = t; i < 4096; i += 256) sW21[i] = W2_1[i];
    if (t < 64) sG[t] = g0[t];
    else if (t < 96) sG[t] = g1[t - 64];
    __syncthreads();

    const float* gns = (const float*)d_g_ns;
    const float* gnv = (const float*)d_g_nv;
    const float* gss = (const float*)d_g_scs;
    const float* gsv = (const float*)d_g_scv;

    int wid = t >> 5, l = t & 31;
    float* acc = sAcc + wid * 480;

    for (int it = 0; it < 8; ++it) {
        int n = blockIdx.x * 64 + it * 8 + wid;
        if (n >= NN) break;
        for (int i = l; i < 480; i += 32)
            acc[i] = (i < 96) ? gns[(size_t)n * 96 + i]
                              : gnv[(size_t)n * 384 + i - 96];
        __syncwarp();

        float vs[2], vv[3];
        float ssq_s = 0.f, ssq_v = 0.f;
#pragma unroll
        for (int r = 0; r < 2; ++r) {
            int o = l + r * 32;
            float a = 0.f;
#pragma unroll 8
            for (int k = 0; k < 96; ++k) a += acc[k] * sW20[k * 64 + o];
            float val = a * 0.1020620726f + gss[(size_t)n * 64 + o];
            vs[r] = val;
            ssq_s += val * val;
        }
#pragma unroll
        for (int r = 0; r < 3; ++r) {
            int o = l + r * 32;
            int up = o / 3, c = o - up * 3;
            float a = 0.f;
#pragma unroll 8
            for (int u = 0; u < 128; ++u) a += acc[96 + c * 128 + u] * sW21[u * 32 + up];
            float val = a * 0.0883883476f + gsv[(size_t)n * 96 + o];
            vv[r] = val;
            ssq_v += val * val;
        }
#pragma unroll
        for (int d = 16; d; d >>= 1) {
            ssq_s += __shfl_xor_sync(0xffffffffu, ssq_s, d);
            ssq_v += __shfl_xor_sync(0xffffffffu, ssq_v, d);
        }
        float rs = rsqrtf(ssq_s * (1.0f / 64.0f) + 1e-5f);
        float rv = rsqrtf(ssq_v * (1.0f / 32.0f) + 1e-5f);
#pragma unroll
        for (int r = 0; r < 2; ++r) {
            int o = l + r * 32;
            out[(size_t)n * 160 + o] = vs[r] * rs * sG[o];
        }
#pragma unroll
        for (int r = 0; r < 3; ++r) {
            int o = l + r * 32;
            out[(size_t)n * 160 + 64 + o] = vv[r] * rv * sG[64 + o / 3];
        }
        __syncwarp();
    }
}

// ---------------- launch ----------------
extern "C" void kernel_launch(void* const* d_in, const int* in_sizes, int n_in,
                              void* d_out, int out_size) {
    const float* nh    = (const float*)d_in[0];
    const int*   ei    = (const int*)  d_in[1];
    const float* esh   = (const float*)d_in[2];
    const float* eattr = (const float*)d_in[3];
    const float* W1_0  = (const float*)d_in[4];
    const float* W1_1  = (const float*)d_in[5];
    const float* Wfc1  = (const float*)d_in[6];
    const float* Wfc2  = (const float*)d_in[7];
    const float* Wfc3  = (const float*)d_in[8];
    const float* W2_0  = (const float*)d_in[9];
    const float* W2_1  = (const float*)d_in[10];
    const float* Wsc0  = (const float*)d_in[11];
    const float* Wsc1  = (const float*)d_in[12];
    const float* g0    = (const float*)d_in[13];
    const float* g1    = (const float*)d_in[14];
    float* out = (float*)d_out;

    cudaFuncSetAttribute(k_edge, cudaFuncAttributeMaxDynamicSharedMemorySize, 57344);
    cudaFuncSetAttribute(k_out, cudaFuncAttributeMaxDynamicSharedMemorySize, 58368);

    k_pre<<<11793, 256>>>(Wfc1, Wfc2, Wfc3);              // zero + transpose
    k_prep<<<391, 256>>>(nh, W1_0, W1_1, Wsc0, Wsc1);     // 64 nodes/block
    k_edge<<<3125, 128, 57344>>>(ei, esh, eattr);
    k_out<<<391, 256, 58368>>>(out, W2_0, W2_1, g0, g1);  // 64 nodes/block
}